// round 12
// baseline (speedup 1.0000x reference)
#include <cuda_runtime.h>
#include <math.h>

#define L_SEQ 4096
#define EDIM  512
#define HDIM  1024
#define G3    3072
#define HROWS 64                     // half-chunk rows
#define NHC   (L_SEQ / HROWS)        // 64 half-chunks
#define NT    24                     // G3/128 column tiles
#define L0CTA 64
#define L1CTA 64
#define GEMCTA 20
#define NFUSED (L0CTA + L1CTA + GEMCTA)   // 148 = #SMs -> single wave

// ---------------- scratch (static device globals; no allocation) -------------
__device__ float g_emb[(size_t)L_SEQ * EDIM];
__device__ float g_gi0[(size_t)L_SEQ * G3];
__device__ float g_gi1[(size_t)L_SEQ * G3];
__device__ float g_ys [(size_t)L_SEQ * HDIM];
__device__ float g_h0[2][HDIM];
__device__ float g_h1[2][HDIM];

struct __align__(128) CtrLine { unsigned v; unsigned pad[31]; };
__device__ CtrLine g_ctrA;   // layer-0 step counter   (+64 per tick)
__device__ CtrLine g_ctrB;   // gi1 half-chunk counter (+20 per hc)
__device__ CtrLine g_ctrC;   // layer-1 step counter   (+64 per tick)
__device__ CtrLine g_ctrD;   // gi0 half-chunk counter (+20 per hc)

// ---------------- memory-model helpers ---------------------------------------
__device__ __forceinline__ unsigned ldacq_u32(const unsigned* p)
{
    unsigned v;
    asm volatile("ld.acquire.gpu.global.b32 %0, [%1];" : "=r"(v) : "l"(p) : "memory");
    return v;
}
__device__ __forceinline__ void red_release_add(unsigned* p, unsigned v)
{
    asm volatile("red.release.gpu.global.add.u32 [%0], %1;" :: "l"(p), "r"(v) : "memory");
}
__device__ __forceinline__ float4 ldacq_v4(const float* p)
{
    float4 v;
    asm volatile("ld.acquire.gpu.global.v4.f32 {%0,%1,%2,%3}, [%4];"
                 : "=f"(v.x), "=f"(v.y), "=f"(v.z), "=f"(v.w) : "l"(p) : "memory");
    return v;
}

// ---------------- packed f32x2 helpers (sm_103a) ------------------------------
__device__ __forceinline__ unsigned long long pack2(float x, float y)
{
    unsigned long long r;
    asm("mov.b64 %0, {%1, %2};" : "=l"(r) : "f"(x), "f"(y));
    return r;
}
__device__ __forceinline__ unsigned long long fma2(unsigned long long a,
                                                   unsigned long long b,
                                                   unsigned long long c)
{
    unsigned long long d;
    asm("fma.rn.f32x2 %0, %1, %2, %3;" : "=l"(d) : "l"(a), "l"(b), "l"(c));
    return d;
}
__device__ __forceinline__ float2 unpack2(unsigned long long v)
{
    float2 f;
    asm("mov.b64 {%0, %1}, %2;" : "=f"(f.x), "=f"(f.y) : "l"(v));
    return f;
}

__device__ __forceinline__ float fsig(float x)
{
    return __fdividef(1.0f, 1.0f + __expf(-x));
}
__device__ __forceinline__ float ftanh(float x)
{
    return 1.0f - __fdividef(2.0f, 1.0f + __expf(2.0f * x));
}

// ---------------- embedding + max-norm --------------------------------------
__global__ void embed_kernel(const int* __restrict__ idx,
                             const float* __restrict__ E,
                             float* __restrict__ emb)
{
    int t = blockIdx.x;
    int id = idx[t];
    const float4* row = (const float4*)(E + (size_t)id * EDIM);
    float4 v = row[threadIdx.x];
    float ss = v.x*v.x + v.y*v.y + v.z*v.z + v.w*v.w;
    #pragma unroll
    for (int o = 16; o; o >>= 1) ss += __shfl_xor_sync(0xffffffffu, ss, o);
    __shared__ float red[4];
    int w = threadIdx.x >> 5;
    if ((threadIdx.x & 31) == 0) red[w] = ss;
    __syncthreads();
    float tot = red[0] + red[1] + red[2] + red[3];
    float scale = fminf(1.0f, 1.0f / fmaxf(sqrtf(tot), 1e-7f));
    v.x *= scale; v.y *= scale; v.z *= scale; v.w *= scale;
    ((float4*)(emb + (size_t)t * EDIM))[threadIdx.x] = v;
}

// ---------------- 64x128 double-buffered f32x2 tile, duplicated-A smem --------
// C[64,128] = A[64,K] @ B[128,K]^T + bias.  256 threads: micro 4x8.
#define AS_W 132
#define BS_W 136

__device__ void gemm_tile64_db(const float* __restrict__ Ab,
                               const float* __restrict__ Bb,
                               const float* __restrict__ bias,
                               float* __restrict__ Cb,
                               int ldc, int K)
{
    __shared__ float AsD[2][16][AS_W];   // duplicated pairs: [k][2*row + {0,1}]
    __shared__ float Bs [2][16][BS_W];
    int tid = threadIdx.x;
    int tx = tid & 15, ty = tid >> 4;

    unsigned long long acc2[4][4];
    #pragma unroll
    for (int r = 0; r < 4; r++)
        #pragma unroll
        for (int j = 0; j < 4; j++) acc2[r][j] = 0ull;

    // A loader: 64 rows x 16 k; one float4 per thread
    int ar = tid >> 2, ac4 = tid & 3;
    // B loader: 128 rows x 16 k; two float4 per thread
    int r0 = tid >> 2,          c0 = tid & 3;
    int r1 = (tid + 256) >> 2,  c1 = tid & 3;

    float4 a0, b0, b1;
    a0 = *(const float4*)(Ab + (size_t)ar * K + ac4 * 4);
    b0 = *(const float4*)(Bb + (size_t)r0 * K + c0 * 4);
    b1 = *(const float4*)(Bb + (size_t)r1 * K + c1 * 4);
    {
        float va[4] = {a0.x, a0.y, a0.z, a0.w};
        #pragma unroll
        for (int i = 0; i < 4; i++)
            *(float2*)&AsD[0][ac4*4+i][2*ar] = make_float2(va[i], va[i]);
        float vb0[4] = {b0.x, b0.y, b0.z, b0.w};
        float vb1[4] = {b1.x, b1.y, b1.z, b1.w};
        #pragma unroll
        for (int i = 0; i < 4; i++) { Bs[0][c0*4+i][r0] = vb0[i]; Bs[0][c1*4+i][r1] = vb1[i]; }
    }
    __syncthreads();

    int nb = K / 16;
    for (int kb = 0; kb < nb; kb++) {
        int buf = kb & 1;
        bool more = (kb + 1 < nb);
        if (more) {
            int k0 = (kb + 1) * 16;
            a0 = *(const float4*)(Ab + (size_t)ar * K + k0 + ac4 * 4);
            b0 = *(const float4*)(Bb + (size_t)r0 * K + k0 + c0 * 4);
            b1 = *(const float4*)(Bb + (size_t)r1 * K + k0 + c1 * 4);
        }
        #pragma unroll
        for (int k = 0; k < 16; k++) {
            ulonglong2 ap0 = *(const ulonglong2*)&AsD[buf][k][ty*8];
            ulonglong2 ap1 = *(const ulonglong2*)&AsD[buf][k][ty*8+4];
            ulonglong2 bq0 = *(const ulonglong2*)&Bs[buf][k][tx*8];
            ulonglong2 bq1 = *(const ulonglong2*)&Bs[buf][k][tx*8+4];
            unsigned long long ap[4] = {ap0.x, ap0.y, ap1.x, ap1.y};
            unsigned long long bp[4] = {bq0.x, bq0.y, bq1.x, bq1.y};
            #pragma unroll
            for (int r = 0; r < 4; r++)
                #pragma unroll
                for (int j = 0; j < 4; j++)
                    acc2[r][j] = fma2(ap[r], bp[j], acc2[r][j]);
        }
        if (more) {
            int nbuf = (kb + 1) & 1;
            float va[4] = {a0.x, a0.y, a0.z, a0.w};
            #pragma unroll
            for (int i = 0; i < 4; i++)
                *(float2*)&AsD[nbuf][ac4*4+i][2*ar] = make_float2(va[i], va[i]);
            float vb0[4] = {b0.x, b0.y, b0.z, b0.w};
            float vb1[4] = {b1.x, b1.y, b1.z, b1.w};
            #pragma unroll
            for (int i = 0; i < 4; i++) { Bs[nbuf][c0*4+i][r0] = vb0[i]; Bs[nbuf][c1*4+i][r1] = vb1[i]; }
            __syncthreads();
        }
    }

    float bb[8];
    #pragma unroll
    for (int j = 0; j < 8; j++) bb[j] = bias[tx*8 + j];
    #pragma unroll
    for (int r = 0; r < 4; r++) {
        size_t row = (size_t)(ty*4 + r);
        float2 e0 = unpack2(acc2[r][0]);
        float2 e1 = unpack2(acc2[r][1]);
        float2 e2 = unpack2(acc2[r][2]);
        float2 e3 = unpack2(acc2[r][3]);
        float4 o0 = make_float4(e0.x+bb[0], e0.y+bb[1], e1.x+bb[2], e1.y+bb[3]);
        float4 o1 = make_float4(e2.x+bb[4], e2.y+bb[5], e3.x+bb[6], e3.y+bb[7]);
        *(float4*)(Cb + row * ldc + tx*8    ) = o0;
        *(float4*)(Cb + row * ldc + tx*8 + 4) = o1;
    }
    __syncthreads();   // smem reuse + orders C stores before tid0's release
}

// produce one 64-row half-chunk of an input projection (this CTA's tiles)
__device__ void produce_half(int g, const float* A, int K,
                             const float* W, const float* bias,
                             float* C, int hc)
{
    for (int tn = g; tn < NT; tn += GEMCTA) {
        gemm_tile64_db(A + (size_t)(hc * HROWS) * K,
                       W + (size_t)(tn * 128) * K,
                       bias + tn * 128,
                       C + (size_t)(hc * HROWS) * G3 + tn * 128,
                       G3, K);
    }
}

// ---------------- fused wavefront kernel --------------------------------------
// CTAs [0,64)    : layer-0 scan (ctrA), gated by ctrD every 64 ticks
// CTAs [64,128)  : layer-1 scan (ctrC), gated by ctrB every 64 ticks
// CTAs [128,148) : GEMM group: pre gi0[hc 0..3]; per hc: gi1[hc], gi0[hc+4]
__global__ void __launch_bounds__(256, 1) fused_kernel(
    const float* __restrict__ Whh0, const float* __restrict__ bhh0,
    const float* __restrict__ Whh1, const float* __restrict__ bhh1,
    const float* __restrict__ Wih0, const float* __restrict__ bih0,
    const float* __restrict__ Wih1, const float* __restrict__ bih1,
    float* __restrict__ out)
{
    int blk = blockIdx.x;
    int tid = threadIdx.x;

    if (blk >= L0CTA + L1CTA) {
        // ---------------- GEMM group ----------------
        int g = blk - (L0CTA + L1CTA);
        for (int hc = 0; hc < 4; hc++) {
            produce_half(g, g_emb, EDIM, Wih0, bih0, g_gi0, hc);
            if (tid == 0) red_release_add(&g_ctrD.v, 1u);
        }
        for (int hc = 0; hc < NHC; hc++) {
            if (tid == 0) {
                unsigned tgt = 64u * (unsigned)(HROWS * (hc + 1));
                while ((int)(ldacq_u32(&g_ctrA.v) - tgt) < 0) { }
            }
            __syncthreads();
            produce_half(g, g_ys, HDIM, Wih1, bih1, g_gi1, hc);
            if (tid == 0) red_release_add(&g_ctrB.v, 1u);
            if (hc + 4 < NHC) {
                produce_half(g, g_emb, EDIM, Wih0, bih0, g_gi0, hc + 4);
                if (tid == 0) red_release_add(&g_ctrD.v, 1u);
            }
        }
        return;
    }

    // ---------------- scan roles ----------------
    int layer = (blk >= L0CTA) ? 1 : 0;
    int cb    = layer ? blk - L0CTA : blk;
    int w     = tid >> 5;
    int lane  = tid & 31;
    int u0    = cb * 16 + 2 * w;               // warp owns units u0, u0+1

    const float* Whh = layer ? Whh1 : Whh0;
    const float* bhh = layer ? bhh1 : bhh0;
    const float* gi  = layer ? g_gi1 : g_gi0;
    unsigned* stepctr  = layer ? &g_ctrC.v : &g_ctrA.v;
    unsigned* chunkctr = layer ? &g_ctrB.v : &g_ctrD.v;

    ulonglong2 wr2[2][8], wz2[2][8], wn2[2][8];
    float br[2], bz[2], bn_[2];
    #pragma unroll
    for (int j = 0; j < 2; j++) {
        const ulonglong2* Wr = (const ulonglong2*)(Whh + (size_t)(u0+j)          * HDIM);
        const ulonglong2* Wz = (const ulonglong2*)(Whh + (size_t)(HDIM   + u0+j) * HDIM);
        const ulonglong2* Wn = (const ulonglong2*)(Whh + (size_t)(2*HDIM + u0+j) * HDIM);
        #pragma unroll
        for (int c = 0; c < 8; c++) {
            wr2[j][c] = Wr[c*32 + lane];
            wz2[j][c] = Wz[c*32 + lane];
            wn2[j][c] = Wn[c*32 + lane];
        }
        br[j]  = bhh[u0+j];
        bz[j]  = bhh[HDIM   + u0+j];
        bn_[j] = bhh[2*HDIM + u0+j];
    }

    __shared__ __align__(16) float h_s[HDIM];
    __shared__ float gi_s[48];
    float hl0 = 0.0f, hl1 = 0.0f;

    for (int t = 0; t < L_SEQ; t++) {
        bool boundary = (t & (HROWS - 1)) == 0;

        // gi prefetch before the poll on non-boundary ticks (chunk confirmed)
        if (!boundary && tid < 48)
            gi_s[tid] = gi[(size_t)t * G3 + (size_t)(tid >> 4) * HDIM + cb*16 + (tid & 15)];

        if (tid == 0) {
            if (boundary) {
                unsigned tb = (unsigned)GEMCTA * ((unsigned)(t >> 6) + 1u);
                while ((int)(ldacq_u32(chunkctr) - tb) < 0) { }
            }
            unsigned tgt = 64u * (unsigned)t;
            while ((int)(ldacq_u32(stepctr) - tgt) < 0) { }
        }
        __syncthreads();                       // bar#1

        if (boundary && tid < 48)
            gi_s[tid] = gi[(size_t)t * G3 + (size_t)(tid >> 4) * HDIM + cb*16 + (tid & 15)];

        const float* hb = layer ? g_h1[t & 1] : g_h0[t & 1];
        float4 hv = ldacq_v4(hb + tid * 4);
        *(float4*)&h_s[tid * 4] = hv;
        __syncthreads();                       // bar#2

        unsigned long long ar2[2] = {0ull, 0ull}, az2[2] = {0ull, 0ull}, an2[2] = {0ull, 0ull};
        #pragma unroll
        for (int c = 0; c < 8; c++) {
            ulonglong2 h2 = *(const ulonglong2*)&h_s[c*128 + lane*4];
            #pragma unroll
            for (int j = 0; j < 2; j++) {
                ar2[j] = fma2(wr2[j][c].x, h2.x, ar2[j]);
                az2[j] = fma2(wz2[j][c].x, h2.x, az2[j]);
                an2[j] = fma2(wn2[j][c].x, h2.x, an2[j]);
                ar2[j] = fma2(wr2[j][c].y, h2.y, ar2[j]);
                az2[j] = fma2(wz2[j][c].y, h2.y, az2[j]);
                an2[j] = fma2(wn2[j][c].y, h2.y, an2[j]);
            }
        }
        float sr[2], sz[2], sn[2];
        #pragma unroll
        for (int j = 0; j < 2; j++) {
            float2 fr = unpack2(ar2[j]); sr[j] = fr.x + fr.y;
            float2 fz = unpack2(az2[j]); sz[j] = fz.x + fz.y;
            float2 fn = unpack2(an2[j]); sn[j] = fn.x + fn.y;
        }
        #pragma unroll
        for (int o = 16; o; o >>= 1) {
            #pragma unroll
            for (int j = 0; j < 2; j++) {
                sr[j] += __shfl_xor_sync(0xffffffffu, sr[j], o);
                sz[j] += __shfl_xor_sync(0xffffffffu, sz[j], o);
                sn[j] += __shfl_xor_sync(0xffffffffu, sn[j], o);
            }
        }

        float hnw[2];
        #pragma unroll
        for (int j = 0; j < 2; j++) {
            float xr = gi_s[      2*w + j];
            float xz = gi_s[16 +  2*w + j];
            float xn = gi_s[32 +  2*w + j];
            float r = fsig(xr + sr[j] + br[j]);
            float z = fsig(xz + sz[j] + bz[j]);
            float n = ftanh(xn + r * (sn[j] + bn_[j]));
            float hp = h_s[u0 + j];
            hnw[j] = (1.0f - z) * n + z * hp;
        }
        if (lane == 0) {
            float* hout = layer ? g_h1[(t + 1) & 1] : g_h0[(t + 1) & 1];
            *(float2*)&hout[u0] = make_float2(hnw[0], hnw[1]);
            if (!layer)
                *(float2*)&g_ys[(size_t)t * HDIM + u0] = make_float2(hnw[0], hnw[1]);
            hl0 = hnw[0]; hl1 = hnw[1];
        }
        __syncthreads();                       // all stores before arrival
        if (tid == 0)
            red_release_add(stepctr, 1u);
    }

    if (lane == 0) {
        if (!layer) {                          // h1 -> out[1024:2048]
            out[HDIM + u0]     = hl0;
            out[HDIM + u0 + 1] = hl1;
        } else {                               // ys2[-1]=h2 -> out[0:1024]; h2 -> out[2048:3072]
            out[u0]     = hl0;
            out[u0 + 1] = hl1;
            out[2*HDIM + u0]     = hl0;
            out[2*HDIM + u0 + 1] = hl1;
        }
    }
}

// reset: h buffers = 0, counters = 0
__global__ void zero_state_kernel()
{
    g_h0[0][threadIdx.x] = 0.0f;
    g_h0[1][threadIdx.x] = 0.0f;
    g_h1[0][threadIdx.x] = 0.0f;
    g_h1[1][threadIdx.x] = 0.0f;
    if (threadIdx.x == 0) {
        g_ctrA.v = 0u;
        g_ctrB.v = 0u;
        g_ctrC.v = 0u;
        g_ctrD.v = 0u;
    }
}

// ---------------- launch -----------------------------------------------------
extern "C" void kernel_launch(void* const* d_in, const int* in_sizes, int n_in,
                              void* d_out, int out_size)
{
    const int*   idx  = (const int*)  d_in[0];
    const float* E    = (const float*)d_in[1];
    const float* Wih0 = (const float*)d_in[2];
    const float* Whh0 = (const float*)d_in[3];
    const float* bih0 = (const float*)d_in[4];
    const float* bhh0 = (const float*)d_in[5];
    const float* Wih1 = (const float*)d_in[6];
    const float* Whh1 = (const float*)d_in[7];
    const float* bih1 = (const float*)d_in[8];
    const float* bhh1 = (const float*)d_in[9];
    float* out = (float*)d_out;

    float *emb;
    cudaGetSymbolAddress((void**)&emb, g_emb);

    // 1) embedding + max-norm
    embed_kernel<<<L_SEQ, 128>>>(idx, E, emb);

    // 2) everything else in one fused wavefront kernel
    zero_state_kernel<<<1, 1024>>>();
    fused_kernel<<<NFUSED, 256>>>(Whh0, bhh0, Whh1, bhh1,
                                  Wih0, bih0, Wih1, bih1, out);
}

// round 13
// speedup vs baseline: 1.7976x; 1.7976x over previous
#include <cuda_runtime.h>
#include <math.h>

#define L_SEQ 4096
#define EDIM  512
#define HDIM  1024
#define G3    3072
#define CHUNK 128
#define NCHUNK (L_SEQ / CHUNK)      // 32
#define L0CTA 64
#define L1CTA 64
#define GEMCTA 20
#define NFUSED (L0CTA + L1CTA + GEMCTA)   // 148 = #SMs -> single wave guaranteed

// ---------------- scratch (static device globals; no allocation) -------------
__device__ float g_emb[(size_t)L_SEQ * EDIM];          // 8 MB
__device__ float g_gi0[(size_t)L_SEQ * G3];            // 50 MB
__device__ float g_gi1[(size_t)L_SEQ * G3];            // 50 MB
__device__ float g_ys [(size_t)L_SEQ * HDIM];          // 16 MB
__device__ float g_h0[2][HDIM];
__device__ float g_h1[2][HDIM];

struct __align__(128) CtrLine { unsigned v; unsigned pad[31]; };
__device__ CtrLine g_ctrA;   // layer-0 step counter  (+64 per tick)
__device__ CtrLine g_ctrB;   // gi1 chunk counter     (+20 per chunk)
__device__ CtrLine g_ctrC;   // layer-1 step counter  (+64 per tick)
__device__ CtrLine g_ctrD;   // gi0 chunk counter     (+20 per chunk)

// ---------------- memory-model helpers ---------------------------------------
__device__ __forceinline__ unsigned ldacq_u32(const unsigned* p)
{
    unsigned v;
    asm volatile("ld.acquire.gpu.global.b32 %0, [%1];" : "=r"(v) : "l"(p) : "memory");
    return v;
}
__device__ __forceinline__ void red_release_add(unsigned* p, unsigned v)
{
    asm volatile("red.release.gpu.global.add.u32 [%0], %1;" :: "l"(p), "r"(v) : "memory");
}
__device__ __forceinline__ float4 ldacq_v4(const float* p)
{
    float4 v;
    asm volatile("ld.acquire.gpu.global.v4.f32 {%0,%1,%2,%3}, [%4];"
                 : "=f"(v.x), "=f"(v.y), "=f"(v.z), "=f"(v.w) : "l"(p) : "memory");
    return v;
}

// ---------------- packed f32x2 helpers (sm_103a) ------------------------------
__device__ __forceinline__ unsigned long long pack2(float x, float y)
{
    unsigned long long r;
    asm("mov.b64 %0, {%1, %2};" : "=l"(r) : "f"(x), "f"(y));
    return r;
}
__device__ __forceinline__ unsigned long long fma2(unsigned long long a,
                                                   unsigned long long b,
                                                   unsigned long long c)
{
    unsigned long long d;
    asm("fma.rn.f32x2 %0, %1, %2, %3;" : "=l"(d) : "l"(a), "l"(b), "l"(c));
    return d;
}
__device__ __forceinline__ float2 unpack2(unsigned long long v)
{
    float2 f;
    asm("mov.b64 {%0, %1}, %2;" : "=f"(f.x), "=f"(f.y) : "l"(v));
    return f;
}

__device__ __forceinline__ float fsig(float x)
{
    return __fdividef(1.0f, 1.0f + __expf(-x));
}
__device__ __forceinline__ float ftanh(float x)
{
    return 1.0f - __fdividef(2.0f, 1.0f + __expf(2.0f * x));
}

// ---------------- embedding + max-norm --------------------------------------
__global__ void embed_kernel(const int* __restrict__ idx,
                             const float* __restrict__ E,
                             float* __restrict__ emb)
{
    int t = blockIdx.x;
    int id = idx[t];
    const float4* row = (const float4*)(E + (size_t)id * EDIM);
    float4 v = row[threadIdx.x];
    float ss = v.x*v.x + v.y*v.y + v.z*v.z + v.w*v.w;
    #pragma unroll
    for (int o = 16; o; o >>= 1) ss += __shfl_xor_sync(0xffffffffu, ss, o);
    __shared__ float red[4];
    int w = threadIdx.x >> 5;
    if ((threadIdx.x & 31) == 0) red[w] = ss;
    __syncthreads();
    float tot = red[0] + red[1] + red[2] + red[3];
    float scale = fminf(1.0f, 1.0f / fmaxf(sqrtf(tot), 1e-7f));
    v.x *= scale; v.y *= scale; v.z *= scale; v.w *= scale;
    ((float4*)(emb + (size_t)t * EDIM))[threadIdx.x] = v;
}

// ---------------- double-buffered f32x2 GEMM tile: 128x128, C = A@B^T + bias --
__device__ void gemm_tile_db(const float* __restrict__ Ab,
                             const float* __restrict__ Bb,
                             const float* __restrict__ bias,
                             float* __restrict__ Cb,
                             int ldc, int K)
{
    __shared__ float As[2][16][128];
    __shared__ float Bs[2][16][136];
    int tid = threadIdx.x;
    int tx = tid & 15, ty = tid >> 4;

    unsigned long long acc2[8][4];
    #pragma unroll
    for (int i = 0; i < 8; i++)
        #pragma unroll
        for (int j = 0; j < 4; j++) acc2[i][j] = 0ull;

    int q0 = tid,        r0 = q0 >> 2, c0 = q0 & 3;
    int q1 = tid + 256,  r1 = q1 >> 2, c1 = q1 & 3;

    float4 ra0, ra1, rb0, rb1;
    ra0 = *(const float4*)(Ab + (size_t)r0 * K + c0 * 4);
    rb0 = *(const float4*)(Bb + (size_t)r0 * K + c0 * 4);
    ra1 = *(const float4*)(Ab + (size_t)r1 * K + c1 * 4);
    rb1 = *(const float4*)(Bb + (size_t)r1 * K + c1 * 4);
    As[0][c0*4+0][r0] = ra0.x; As[0][c0*4+1][r0] = ra0.y; As[0][c0*4+2][r0] = ra0.z; As[0][c0*4+3][r0] = ra0.w;
    Bs[0][c0*4+0][r0] = rb0.x; Bs[0][c0*4+1][r0] = rb0.y; Bs[0][c0*4+2][r0] = rb0.z; Bs[0][c0*4+3][r0] = rb0.w;
    As[0][c1*4+0][r1] = ra1.x; As[0][c1*4+1][r1] = ra1.y; As[0][c1*4+2][r1] = ra1.z; As[0][c1*4+3][r1] = ra1.w;
    Bs[0][c1*4+0][r1] = rb1.x; Bs[0][c1*4+1][r1] = rb1.y; Bs[0][c1*4+2][r1] = rb1.z; Bs[0][c1*4+3][r1] = rb1.w;
    __syncthreads();

    int nb = K / 16;
    for (int kb = 0; kb < nb; kb++) {
        int buf = kb & 1;
        bool more = (kb + 1 < nb);
        if (more) {
            int k0 = (kb + 1) * 16;
            ra0 = *(const float4*)(Ab + (size_t)r0 * K + k0 + c0 * 4);
            rb0 = *(const float4*)(Bb + (size_t)r0 * K + k0 + c0 * 4);
            ra1 = *(const float4*)(Ab + (size_t)r1 * K + k0 + c1 * 4);
            rb1 = *(const float4*)(Bb + (size_t)r1 * K + k0 + c1 * 4);
        }
        #pragma unroll
        for (int k = 0; k < 16; k++) {
            float4 a0 = *(const float4*)&As[buf][k][ty*8];
            float4 a1 = *(const float4*)&As[buf][k][ty*8+4];
            float4 b0 = *(const float4*)&Bs[buf][k][tx*8];
            float4 b1 = *(const float4*)&Bs[buf][k][tx*8+4];
            float av[8] = {a0.x,a0.y,a0.z,a0.w,a1.x,a1.y,a1.z,a1.w};
            unsigned long long bp[4] = { pack2(b0.x,b0.y), pack2(b0.z,b0.w),
                                         pack2(b1.x,b1.y), pack2(b1.z,b1.w) };
            #pragma unroll
            for (int i = 0; i < 8; i++) {
                unsigned long long ad = pack2(av[i], av[i]);
                #pragma unroll
                for (int j = 0; j < 4; j++)
                    acc2[i][j] = fma2(ad, bp[j], acc2[i][j]);
            }
        }
        if (more) {
            int nbuf = (kb + 1) & 1;
            As[nbuf][c0*4+0][r0] = ra0.x; As[nbuf][c0*4+1][r0] = ra0.y; As[nbuf][c0*4+2][r0] = ra0.z; As[nbuf][c0*4+3][r0] = ra0.w;
            Bs[nbuf][c0*4+0][r0] = rb0.x; Bs[nbuf][c0*4+1][r0] = rb0.y; Bs[nbuf][c0*4+2][r0] = rb0.z; Bs[nbuf][c0*4+3][r0] = rb0.w;
            As[nbuf][c1*4+0][r1] = ra1.x; As[nbuf][c1*4+1][r1] = ra1.y; As[nbuf][c1*4+2][r1] = ra1.z; As[nbuf][c1*4+3][r1] = ra1.w;
            Bs[nbuf][c1*4+0][r1] = rb1.x; Bs[nbuf][c1*4+1][r1] = rb1.y; Bs[nbuf][c1*4+2][r1] = rb1.z; Bs[nbuf][c1*4+3][r1] = rb1.w;
            __syncthreads();
        }
    }

    float bb[8];
    #pragma unroll
    for (int j = 0; j < 8; j++) bb[j] = bias[tx*8 + j];
    #pragma unroll
    for (int i = 0; i < 8; i++) {
        size_t row = (size_t)(ty*8 + i);
        float2 e0 = unpack2(acc2[i][0]);
        float2 e1 = unpack2(acc2[i][1]);
        float2 e2 = unpack2(acc2[i][2]);
        float2 e3 = unpack2(acc2[i][3]);
        float4 o0 = make_float4(e0.x+bb[0], e0.y+bb[1], e1.x+bb[2], e1.y+bb[3]);
        float4 o1 = make_float4(e2.x+bb[4], e2.y+bb[5], e3.x+bb[6], e3.y+bb[7]);
        *(float4*)(Cb + row * ldc + tx*8    ) = o0;
        *(float4*)(Cb + row * ldc + tx*8 + 4) = o1;
    }
    __syncthreads();   // smem safe for next tile; orders C stores before release
}

// produce one 128-token chunk of an input projection
__device__ void produce_chunk(int g, const float* A, int K,
                              const float* W, const float* bias,
                              float* C, int ch)
{
    for (int tn = g; tn < G3 / 128; tn += GEMCTA) {
        gemm_tile_db(A + (size_t)(ch * CHUNK) * K,
                     W + (size_t)(tn * 128) * K,
                     bias + tn * 128,
                     C + (size_t)(ch * CHUNK) * G3 + tn * 128,
                     G3, K);
    }
}

// ---------------- fused wavefront kernel --------------------------------------
// CTAs [0,64)    : layer-0 scan (ctrA), gated by ctrD at chunk boundaries
// CTAs [64,128)  : layer-1 scan (ctrC), gated by ctrB at chunk boundaries
// CTAs [128,148) : GEMM group: pre gi0[0..1]; per ch: gi1[ch], gi0[ch+2]
__global__ void __launch_bounds__(256, 1) fused_kernel(
    const float* __restrict__ Whh0, const float* __restrict__ bhh0,
    const float* __restrict__ Whh1, const float* __restrict__ bhh1,
    const float* __restrict__ Wih0, const float* __restrict__ bih0,
    const float* __restrict__ Wih1, const float* __restrict__ bih1,
    float* __restrict__ out)
{
    int blk = blockIdx.x;
    int tid = threadIdx.x;

    if (blk >= L0CTA + L1CTA) {
        // ---------------- GEMM group ----------------
        int g = blk - (L0CTA + L1CTA);
        for (int ch = 0; ch < 2; ch++) {
            produce_chunk(g, g_emb, EDIM, Wih0, bih0, g_gi0, ch);
            if (tid == 0) red_release_add(&g_ctrD.v, 1u);
        }
        for (int ch = 0; ch < NCHUNK; ch++) {
            if (tid == 0) {
                unsigned tgt = 64u * (unsigned)(CHUNK * (ch + 1));
                while ((int)(ldacq_u32(&g_ctrA.v) - tgt) < 0) { }
            }
            __syncthreads();
            produce_chunk(g, g_ys, HDIM, Wih1, bih1, g_gi1, ch);
            if (tid == 0) red_release_add(&g_ctrB.v, 1u);
            if (ch + 2 < NCHUNK) {
                produce_chunk(g, g_emb, EDIM, Wih0, bih0, g_gi0, ch + 2);
                if (tid == 0) red_release_add(&g_ctrD.v, 1u);
            }
        }
        return;
    }

    // ---------------- scan roles ----------------
    int layer = (blk >= L0CTA) ? 1 : 0;
    int cb    = layer ? blk - L0CTA : blk;
    int w     = tid >> 5;
    int lane  = tid & 31;
    int u0    = cb * 16 + 2 * w;               // warp owns units u0, u0+1

    const float* Whh = layer ? Whh1 : Whh0;
    const float* bhh = layer ? bhh1 : bhh0;
    const float* gi  = layer ? g_gi1 : g_gi0;
    unsigned* stepctr  = layer ? &g_ctrC.v : &g_ctrA.v;
    unsigned* chunkctr = layer ? &g_ctrB.v : &g_ctrD.v;

    ulonglong2 wr2[2][8], wz2[2][8], wn2[2][8];
    float br[2], bz[2], bn_[2];
    #pragma unroll
    for (int j = 0; j < 2; j++) {
        const ulonglong2* Wr = (const ulonglong2*)(Whh + (size_t)(u0+j)          * HDIM);
        const ulonglong2* Wz = (const ulonglong2*)(Whh + (size_t)(HDIM   + u0+j) * HDIM);
        const ulonglong2* Wn = (const ulonglong2*)(Whh + (size_t)(2*HDIM + u0+j) * HDIM);
        #pragma unroll
        for (int c = 0; c < 8; c++) {
            wr2[j][c] = Wr[c*32 + lane];
            wz2[j][c] = Wz[c*32 + lane];
            wn2[j][c] = Wn[c*32 + lane];
        }
        br[j]  = bhh[u0+j];
        bz[j]  = bhh[HDIM   + u0+j];
        bn_[j] = bhh[2*HDIM + u0+j];
    }

    __shared__ __align__(16) float h_s[HDIM];
    __shared__ float gi_s[2][48];              // double-buffered (pipelined)
    float hl0 = 0.0f, hl1 = 0.0f;

    // my gi address for tick t: gi[t*G3 + (tid/16)*HDIM + cb*16 + (tid&15)]
    size_t gi_off = (size_t)(tid >> 4) * HDIM + cb * 16 + (tid & 15);

    for (int t = 0; t < L_SEQ; t++) {
        bool boundary = (t & (CHUNK - 1)) == 0;
        // can we prefetch gi(t+1) during this tick? (same chunk => already gated)
        bool pre_next = ((t + 1) & (CHUNK - 1)) != 0 && (t + 1) < L_SEQ;

        if (tid == 0) {
            if (boundary) {
                unsigned tb = (unsigned)GEMCTA * ((unsigned)(t >> 7) + 1u);
                while ((int)(ldacq_u32(chunkctr) - tb) < 0) { }
            }
            unsigned tgt = 64u * (unsigned)t;
            while ((int)(ldacq_u32(stepctr) - tgt) < 0) { }
        }
        __syncthreads();                       // bar#1

        // boundary ticks: gi(t) not prefetched (chunk only just confirmed):
        // load it synchronously now (32 of 4096 ticks)
        if (boundary && tid < 48)
            gi_s[t & 1][tid] = gi[(size_t)t * G3 + gi_off];

        const float* hb = layer ? g_h1[t & 1] : g_h0[t & 1];
        float4 hv = ldacq_v4(hb + tid * 4);
        *(float4*)&h_s[tid * 4] = hv;
        __syncthreads();                       // bar#2

        // issue next tick's gi load NOW; it completes under ~1us of compute
        float gnext = 0.0f;
        if (pre_next && tid < 48)
            gnext = gi[(size_t)(t + 1) * G3 + gi_off];

        unsigned long long ar2[2] = {0ull, 0ull}, az2[2] = {0ull, 0ull}, an2[2] = {0ull, 0ull};
        #pragma unroll
        for (int c = 0; c < 8; c++) {
            ulonglong2 h2 = *(const ulonglong2*)&h_s[c*128 + lane*4];
            #pragma unroll
            for (int j = 0; j < 2; j++) {
                ar2[j] = fma2(wr2[j][c].x, h2.x, ar2[j]);
                az2[j] = fma2(wz2[j][c].x, h2.x, az2[j]);
                an2[j] = fma2(wn2[j][c].x, h2.x, an2[j]);
                ar2[j] = fma2(wr2[j][c].y, h2.y, ar2[j]);
                az2[j] = fma2(wz2[j][c].y, h2.y, az2[j]);
                an2[j] = fma2(wn2[j][c].y, h2.y, an2[j]);
            }
        }
        float sr[2], sz[2], sn[2];
        #pragma unroll
        for (int j = 0; j < 2; j++) {
            float2 fr = unpack2(ar2[j]); sr[j] = fr.x + fr.y;
            float2 fz = unpack2(az2[j]); sz[j] = fz.x + fz.y;
            float2 fn = unpack2(an2[j]); sn[j] = fn.x + fn.y;
        }
        #pragma unroll
        for (int o = 16; o; o >>= 1) {
            #pragma unroll
            for (int j = 0; j < 2; j++) {
                sr[j] += __shfl_xor_sync(0xffffffffu, sr[j], o);
                sz[j] += __shfl_xor_sync(0xffffffffu, sz[j], o);
                sn[j] += __shfl_xor_sync(0xffffffffu, sn[j], o);
            }
        }

        // stage next tick's gi into the other smem buffer (visible after bar#3)
        if (pre_next && tid < 48)
            gi_s[(t + 1) & 1][tid] = gnext;

        float hnw[2];
        #pragma unroll
        for (int j = 0; j < 2; j++) {
            float xr = gi_s[t & 1][      2*w + j];
            float xz = gi_s[t & 1][16 +  2*w + j];
            float xn = gi_s[t & 1][32 +  2*w + j];
            float r = fsig(xr + sr[j] + br[j]);
            float z = fsig(xz + sz[j] + bz[j]);
            float n = ftanh(xn + r * (sn[j] + bn_[j]));
            float hp = h_s[u0 + j];
            hnw[j] = (1.0f - z) * n + z * hp;
        }
        if (lane == 0) {
            float* hout = layer ? g_h1[(t + 1) & 1] : g_h0[(t + 1) & 1];
            *(float2*)&hout[u0] = make_float2(hnw[0], hnw[1]);
            if (!layer)
                *(float2*)&g_ys[(size_t)t * HDIM + u0] = make_float2(hnw[0], hnw[1]);
            hl0 = hnw[0]; hl1 = hnw[1];
        }
        __syncthreads();                       // bar#3: stores + gi stage visible
        if (tid == 0)
            red_release_add(stepctr, 1u);
    }

    if (lane == 0) {
        if (!layer) {                          // h1 -> out[1024:2048]
            out[HDIM + u0]     = hl0;
            out[HDIM + u0 + 1] = hl1;
        } else {                               // ys2[-1]=h2 -> out[0:1024]; h2 -> out[2048:3072]
            out[u0]     = hl0;
            out[u0 + 1] = hl1;
            out[2*HDIM + u0]     = hl0;
            out[2*HDIM + u0 + 1] = hl1;
        }
    }
}

// reset: h buffers = 0, counters = 0
__global__ void zero_state_kernel()
{
    g_h0[0][threadIdx.x] = 0.0f;
    g_h0[1][threadIdx.x] = 0.0f;
    g_h1[0][threadIdx.x] = 0.0f;
    g_h1[1][threadIdx.x] = 0.0f;
    if (threadIdx.x == 0) {
        g_ctrA.v = 0u;
        g_ctrB.v = 0u;
        g_ctrC.v = 0u;
        g_ctrD.v = 0u;
    }
}

// ---------------- launch -----------------------------------------------------
extern "C" void kernel_launch(void* const* d_in, const int* in_sizes, int n_in,
                              void* d_out, int out_size)
{
    const int*   idx  = (const int*)  d_in[0];
    const float* E    = (const float*)d_in[1];
    const float* Wih0 = (const float*)d_in[2];
    const float* Whh0 = (const float*)d_in[3];
    const float* bih0 = (const float*)d_in[4];
    const float* bhh0 = (const float*)d_in[5];
    const float* Wih1 = (const float*)d_in[6];
    const float* Whh1 = (const float*)d_in[7];
    const float* bih1 = (const float*)d_in[8];
    const float* bhh1 = (const float*)d_in[9];
    float* out = (float*)d_out;

    float *emb;
    cudaGetSymbolAddress((void**)&emb, g_emb);

    // 1) embedding + max-norm
    embed_kernel<<<L_SEQ, 128>>>(idx, E, emb);

    // 2) everything else in one fused wavefront kernel
    zero_state_kernel<<<1, 1024>>>();
    fused_kernel<<<NFUSED, 256>>>(Whh0, bhh0, Whh1, bhh1,
                                  Wih0, bih0, Wih1, bih1, out);
}

// round 14
// speedup vs baseline: 1.8035x; 1.0033x over previous
#include <cuda_runtime.h>
#include <math.h>

#define L_SEQ 4096
#define EDIM  512
#define HDIM  1024
#define G3    3072
#define CHUNK 128
#define NCHUNK (L_SEQ / CHUNK)      // 32
#define L0CTA 64
#define L1CTA 64
#define GEMCTA 20
#define NFUSED (L0CTA + L1CTA + GEMCTA)   // 148 = #SMs -> single wave guaranteed

// ---------------- scratch (static device globals; no allocation) -------------
__device__ float g_emb[(size_t)L_SEQ * EDIM];          // 8 MB
__device__ float g_gi0[(size_t)L_SEQ * G3];            // 50 MB
__device__ float g_gi1[(size_t)L_SEQ * G3];            // 50 MB
__device__ float g_ys [(size_t)L_SEQ * HDIM];          // 16 MB
__device__ float g_h0[2][HDIM];
__device__ float g_h1[2][HDIM];

struct __align__(128) CtrLine { unsigned v; unsigned pad[31]; };
__device__ CtrLine g_ctrA;   // layer-0 step counter  (+64 per tick)
__device__ CtrLine g_ctrB;   // gi1 chunk counter     (+20 per chunk)
__device__ CtrLine g_ctrC;   // layer-1 step counter  (+64 per tick)
__device__ CtrLine g_ctrD;   // gi0 chunk counter     (+20 per chunk)

// ---------------- memory-model helpers ---------------------------------------
__device__ __forceinline__ unsigned ldacq_u32(const unsigned* p)
{
    unsigned v;
    asm volatile("ld.acquire.gpu.global.b32 %0, [%1];" : "=r"(v) : "l"(p) : "memory");
    return v;
}
__device__ __forceinline__ void red_release_add(unsigned* p, unsigned v)
{
    asm volatile("red.release.gpu.global.add.u32 [%0], %1;" :: "l"(p), "r"(v) : "memory");
}
__device__ __forceinline__ float4 ldacq_v4(const float* p)
{
    float4 v;
    asm volatile("ld.acquire.gpu.global.v4.f32 {%0,%1,%2,%3}, [%4];"
                 : "=f"(v.x), "=f"(v.y), "=f"(v.z), "=f"(v.w) : "l"(p) : "memory");
    return v;
}

// ---------------- packed f32x2 helpers (sm_103a) ------------------------------
__device__ __forceinline__ unsigned long long pack2(float x, float y)
{
    unsigned long long r;
    asm("mov.b64 %0, {%1, %2};" : "=l"(r) : "f"(x), "f"(y));
    return r;
}
__device__ __forceinline__ unsigned long long fma2(unsigned long long a,
                                                   unsigned long long b,
                                                   unsigned long long c)
{
    unsigned long long d;
    asm("fma.rn.f32x2 %0, %1, %2, %3;" : "=l"(d) : "l"(a), "l"(b), "l"(c));
    return d;
}
__device__ __forceinline__ float2 unpack2(unsigned long long v)
{
    float2 f;
    asm("mov.b64 {%0, %1}, %2;" : "=f"(f.x), "=f"(f.y) : "l"(v));
    return f;
}

__device__ __forceinline__ float fsig(float x)
{
    return __fdividef(1.0f, 1.0f + __expf(-x));
}
__device__ __forceinline__ float ftanh(float x)
{
    return 1.0f - __fdividef(2.0f, 1.0f + __expf(2.0f * x));
}

// ---------------- embedding + max-norm --------------------------------------
__global__ void embed_kernel(const int* __restrict__ idx,
                             const float* __restrict__ E,
                             float* __restrict__ emb)
{
    int t = blockIdx.x;
    int id = idx[t];
    const float4* row = (const float4*)(E + (size_t)id * EDIM);
    float4 v = row[threadIdx.x];
    float ss = v.x*v.x + v.y*v.y + v.z*v.z + v.w*v.w;
    #pragma unroll
    for (int o = 16; o; o >>= 1) ss += __shfl_xor_sync(0xffffffffu, ss, o);
    __shared__ float red[4];
    int w = threadIdx.x >> 5;
    if ((threadIdx.x & 31) == 0) red[w] = ss;
    __syncthreads();
    float tot = red[0] + red[1] + red[2] + red[3];
    float scale = fminf(1.0f, 1.0f / fmaxf(sqrtf(tot), 1e-7f));
    v.x *= scale; v.y *= scale; v.z *= scale; v.w *= scale;
    ((float4*)(emb + (size_t)t * EDIM))[threadIdx.x] = v;
}

// ---------------- double-buffered f32x2 GEMM tile: 128x128, C = A@B^T + bias --
__device__ void gemm_tile_db(const float* __restrict__ Ab,
                             const float* __restrict__ Bb,
                             const float* __restrict__ bias,
                             float* __restrict__ Cb,
                             int ldc, int K)
{
    __shared__ float As[2][16][128];
    __shared__ float Bs[2][16][136];
    int tid = threadIdx.x;
    int tx = tid & 15, ty = tid >> 4;

    unsigned long long acc2[8][4];
    #pragma unroll
    for (int i = 0; i < 8; i++)
        #pragma unroll
        for (int j = 0; j < 4; j++) acc2[i][j] = 0ull;

    int q0 = tid,        r0 = q0 >> 2, c0 = q0 & 3;
    int q1 = tid + 256,  r1 = q1 >> 2, c1 = q1 & 3;

    float4 ra0, ra1, rb0, rb1;
    ra0 = *(const float4*)(Ab + (size_t)r0 * K + c0 * 4);
    rb0 = *(const float4*)(Bb + (size_t)r0 * K + c0 * 4);
    ra1 = *(const float4*)(Ab + (size_t)r1 * K + c1 * 4);
    rb1 = *(const float4*)(Bb + (size_t)r1 * K + c1 * 4);
    As[0][c0*4+0][r0] = ra0.x; As[0][c0*4+1][r0] = ra0.y; As[0][c0*4+2][r0] = ra0.z; As[0][c0*4+3][r0] = ra0.w;
    Bs[0][c0*4+0][r0] = rb0.x; Bs[0][c0*4+1][r0] = rb0.y; Bs[0][c0*4+2][r0] = rb0.z; Bs[0][c0*4+3][r0] = rb0.w;
    As[0][c1*4+0][r1] = ra1.x; As[0][c1*4+1][r1] = ra1.y; As[0][c1*4+2][r1] = ra1.z; As[0][c1*4+3][r1] = ra1.w;
    Bs[0][c1*4+0][r1] = rb1.x; Bs[0][c1*4+1][r1] = rb1.y; Bs[0][c1*4+2][r1] = rb1.z; Bs[0][c1*4+3][r1] = rb1.w;
    __syncthreads();

    int nb = K / 16;
    for (int kb = 0; kb < nb; kb++) {
        int buf = kb & 1;
        bool more = (kb + 1 < nb);
        if (more) {
            int k0 = (kb + 1) * 16;
            ra0 = *(const float4*)(Ab + (size_t)r0 * K + k0 + c0 * 4);
            rb0 = *(const float4*)(Bb + (size_t)r0 * K + k0 + c0 * 4);
            ra1 = *(const float4*)(Ab + (size_t)r1 * K + k0 + c1 * 4);
            rb1 = *(const float4*)(Bb + (size_t)r1 * K + k0 + c1 * 4);
        }
        #pragma unroll
        for (int k = 0; k < 16; k++) {
            float4 a0 = *(const float4*)&As[buf][k][ty*8];
            float4 a1 = *(const float4*)&As[buf][k][ty*8+4];
            float4 b0 = *(const float4*)&Bs[buf][k][tx*8];
            float4 b1 = *(const float4*)&Bs[buf][k][tx*8+4];
            float av[8] = {a0.x,a0.y,a0.z,a0.w,a1.x,a1.y,a1.z,a1.w};
            unsigned long long bp[4] = { pack2(b0.x,b0.y), pack2(b0.z,b0.w),
                                         pack2(b1.x,b1.y), pack2(b1.z,b1.w) };
            #pragma unroll
            for (int i = 0; i < 8; i++) {
                unsigned long long ad = pack2(av[i], av[i]);
                #pragma unroll
                for (int j = 0; j < 4; j++)
                    acc2[i][j] = fma2(ad, bp[j], acc2[i][j]);
            }
        }
        if (more) {
            int nbuf = (kb + 1) & 1;
            As[nbuf][c0*4+0][r0] = ra0.x; As[nbuf][c0*4+1][r0] = ra0.y; As[nbuf][c0*4+2][r0] = ra0.z; As[nbuf][c0*4+3][r0] = ra0.w;
            Bs[nbuf][c0*4+0][r0] = rb0.x; Bs[nbuf][c0*4+1][r0] = rb0.y; Bs[nbuf][c0*4+2][r0] = rb0.z; Bs[nbuf][c0*4+3][r0] = rb0.w;
            As[nbuf][c1*4+0][r1] = ra1.x; As[nbuf][c1*4+1][r1] = ra1.y; As[nbuf][c1*4+2][r1] = ra1.z; As[nbuf][c1*4+3][r1] = ra1.w;
            Bs[nbuf][c1*4+0][r1] = rb1.x; Bs[nbuf][c1*4+1][r1] = rb1.y; Bs[nbuf][c1*4+2][r1] = rb1.z; Bs[nbuf][c1*4+3][r1] = rb1.w;
            __syncthreads();
        }
    }

    float bb[8];
    #pragma unroll
    for (int j = 0; j < 8; j++) bb[j] = bias[tx*8 + j];
    #pragma unroll
    for (int i = 0; i < 8; i++) {
        size_t row = (size_t)(ty*8 + i);
        float2 e0 = unpack2(acc2[i][0]);
        float2 e1 = unpack2(acc2[i][1]);
        float2 e2 = unpack2(acc2[i][2]);
        float2 e3 = unpack2(acc2[i][3]);
        float4 o0 = make_float4(e0.x+bb[0], e0.y+bb[1], e1.x+bb[2], e1.y+bb[3]);
        float4 o1 = make_float4(e2.x+bb[4], e2.y+bb[5], e3.x+bb[6], e3.y+bb[7]);
        *(float4*)(Cb + row * ldc + tx*8    ) = o0;
        *(float4*)(Cb + row * ldc + tx*8 + 4) = o1;
    }
    __syncthreads();   // smem safe for next tile; orders C stores before release
}

// produce one 128-token chunk of an input projection
__device__ void produce_chunk(int g, const float* A, int K,
                              const float* W, const float* bias,
                              float* C, int ch)
{
    for (int tn = g; tn < G3 / 128; tn += GEMCTA) {
        gemm_tile_db(A + (size_t)(ch * CHUNK) * K,
                     W + (size_t)(tn * 128) * K,
                     bias + tn * 128,
                     C + (size_t)(ch * CHUNK) * G3 + tn * 128,
                     G3, K);
    }
}

// ---------------- fused wavefront kernel --------------------------------------
// CTAs [0,64)    : layer-0 scan (ctrA), gated by ctrD at chunk boundaries
// CTAs [64,128)  : layer-1 scan (ctrC), gated by ctrB at chunk boundaries
// CTAs [128,148) : GEMM group: pre gi0[0..1]; per ch: gi1[ch], gi0[ch+2]
// Scan reduction: HALF-WARP per unit (12 shfl / 4 levels, was 30 / 5).
__global__ void __launch_bounds__(256, 1) fused_kernel(
    const float* __restrict__ Whh0, const float* __restrict__ bhh0,
    const float* __restrict__ Whh1, const float* __restrict__ bhh1,
    const float* __restrict__ Wih0, const float* __restrict__ bih0,
    const float* __restrict__ Wih1, const float* __restrict__ bih1,
    float* __restrict__ out)
{
    int blk = blockIdx.x;
    int tid = threadIdx.x;

    if (blk >= L0CTA + L1CTA) {
        // ---------------- GEMM group ----------------
        int g = blk - (L0CTA + L1CTA);
        for (int ch = 0; ch < 2; ch++) {
            produce_chunk(g, g_emb, EDIM, Wih0, bih0, g_gi0, ch);
            if (tid == 0) red_release_add(&g_ctrD.v, 1u);
        }
        for (int ch = 0; ch < NCHUNK; ch++) {
            if (tid == 0) {
                unsigned tgt = 64u * (unsigned)(CHUNK * (ch + 1));
                while ((int)(ldacq_u32(&g_ctrA.v) - tgt) < 0) { }
            }
            __syncthreads();
            produce_chunk(g, g_ys, HDIM, Wih1, bih1, g_gi1, ch);
            if (tid == 0) red_release_add(&g_ctrB.v, 1u);
            if (ch + 2 < NCHUNK) {
                produce_chunk(g, g_emb, EDIM, Wih0, bih0, g_gi0, ch + 2);
                if (tid == 0) red_release_add(&g_ctrD.v, 1u);
            }
        }
        return;
    }

    // ---------------- scan roles ----------------
    int layer = (blk >= L0CTA) ? 1 : 0;
    int cb    = layer ? blk - L0CTA : blk;
    int w     = tid >> 5;
    int lane  = tid & 31;
    int hl    = lane & 15;                    // lane within half-warp
    int jj    = lane >> 4;                    // which unit of the pair
    int u0    = cb * 16 + 2 * w;              // warp owns units u0, u0+1
    int unit  = u0 + jj;                      // this half-warp's unit

    const float* Whh = layer ? Whh1 : Whh0;
    const float* bhh = layer ? bhh1 : bhh0;
    const float* gi  = layer ? g_gi1 : g_gi0;
    unsigned* stepctr  = layer ? &g_ctrC.v : &g_ctrA.v;
    unsigned* chunkctr = layer ? &g_ctrB.v : &g_ctrD.v;

    // weights for THIS half-warp's unit: lane hl covers h[c*64 + hl*4 .. +4)
    const ulonglong2* Wr = (const ulonglong2*)(Whh + (size_t)unit            * HDIM);
    const ulonglong2* Wz = (const ulonglong2*)(Whh + (size_t)(HDIM   + unit) * HDIM);
    const ulonglong2* Wn = (const ulonglong2*)(Whh + (size_t)(2*HDIM + unit) * HDIM);
    ulonglong2 wr2[16], wz2[16], wn2[16];
    #pragma unroll
    for (int c = 0; c < 16; c++) {
        wr2[c] = Wr[c*16 + hl];
        wz2[c] = Wz[c*16 + hl];
        wn2[c] = Wn[c*16 + hl];
    }
    float br  = bhh[unit];
    float bz  = bhh[HDIM   + unit];
    float bn_ = bhh[2*HDIM + unit];

    __shared__ __align__(16) float h_s[HDIM];
    __shared__ float gi_s[2][48];              // double-buffered (pipelined)
    float h_last = 0.0f;

    // my gi address for tick t: gi[t*G3 + (tid/16)*HDIM + cb*16 + (tid&15)]
    size_t gi_off = (size_t)(tid >> 4) * HDIM + cb * 16 + (tid & 15);

    for (int t = 0; t < L_SEQ; t++) {
        bool boundary = (t & (CHUNK - 1)) == 0;
        bool pre_next = ((t + 1) & (CHUNK - 1)) != 0 && (t + 1) < L_SEQ;

        // warp 0: chunk gate (rare) + 4-lane cooperative step poll
        if (w == 0) {
            if (boundary && lane == 0) {
                unsigned tb = (unsigned)GEMCTA * ((unsigned)(t >> 7) + 1u);
                while ((int)(ldacq_u32(chunkctr) - tb) < 0) { }
            }
            __syncwarp();
            unsigned tgt = 64u * (unsigned)t;
            for (;;) {
                unsigned v = (lane < 4) ? ldacq_u32(stepctr) : 0u;
                bool sat = (lane < 4) && ((int)(v - tgt) >= 0);
                if (__any_sync(0xffffffffu, sat)) break;
            }
        }
        __syncthreads();                       // bar#1

        // boundary ticks: gi(t) not prefetched; load now (32 of 4096 ticks)
        if (boundary && tid < 48)
            gi_s[t & 1][tid] = gi[(size_t)t * G3 + gi_off];

        const float* hb = layer ? g_h1[t & 1] : g_h0[t & 1];
        float4 hv = ldacq_v4(hb + tid * 4);
        *(float4*)&h_s[tid * 4] = hv;
        __syncthreads();                       // bar#2

        // issue next tick's gi load now (completes under compute)
        float gnext = 0.0f;
        if (pre_next && tid < 48)
            gnext = gi[(size_t)(t + 1) * G3 + gi_off];

        // half-warp dot products: 96 FMA2/lane over 16 chunks of 64 h-values
        unsigned long long ar2 = 0ull, az2 = 0ull, an2 = 0ull;
        #pragma unroll
        for (int c = 0; c < 16; c++) {
            ulonglong2 h2 = *(const ulonglong2*)&h_s[c*64 + hl*4];
            ar2 = fma2(wr2[c].x, h2.x, ar2);
            az2 = fma2(wz2[c].x, h2.x, az2);
            an2 = fma2(wn2[c].x, h2.x, an2);
            ar2 = fma2(wr2[c].y, h2.y, ar2);
            az2 = fma2(wz2[c].y, h2.y, az2);
            an2 = fma2(wn2[c].y, h2.y, an2);
        }
        float2 fr = unpack2(ar2);
        float2 fz = unpack2(az2);
        float2 fn = unpack2(an2);
        float sr = fr.x + fr.y;
        float sz = fz.x + fz.y;
        float sn = fn.x + fn.y;
        #pragma unroll
        for (int o = 8; o; o >>= 1) {          // 4 levels within the half-warp
            sr += __shfl_xor_sync(0xffffffffu, sr, o);
            sz += __shfl_xor_sync(0xffffffffu, sz, o);
            sn += __shfl_xor_sync(0xffffffffu, sn, o);
        }

        // stage next tick's gi (visible after bar#3)
        if (pre_next && tid < 48)
            gi_s[(t + 1) & 1][tid] = gnext;

        // gates (all lanes of the half-warp redundantly)
        float xr = gi_s[t & 1][      2*w + jj];
        float xz = gi_s[t & 1][16 +  2*w + jj];
        float xn = gi_s[t & 1][32 +  2*w + jj];
        float r = fsig(xr + sr + br);
        float z = fsig(xz + sz + bz);
        float n = ftanh(xn + r * (sn + bn_));
        float hp = h_s[unit];
        float hnw = (1.0f - z) * n + z * hp;
        if (hl == 0) {                         // lanes 0 and 16 publish
            float* hout = layer ? g_h1[(t + 1) & 1] : g_h0[(t + 1) & 1];
            hout[unit] = hnw;
            if (!layer) g_ys[(size_t)t * HDIM + unit] = hnw;
            h_last = hnw;
        }
        __syncthreads();                       // bar#3: stores + gi stage visible
        if (tid == 0)
            red_release_add(stepctr, 1u);
    }

    if (hl == 0) {
        if (!layer) {                          // h1 -> out[1024:2048]
            out[HDIM + unit] = h_last;
        } else {                               // ys2[-1]=h2 -> out[0:1024]; h2 -> out[2048:3072]
            out[unit]          = h_last;
            out[2*HDIM + unit] = h_last;
        }
    }
}

// reset: h buffers = 0, counters = 0
__global__ void zero_state_kernel()
{
    g_h0[0][threadIdx.x] = 0.0f;
    g_h0[1][threadIdx.x] = 0.0f;
    g_h1[0][threadIdx.x] = 0.0f;
    g_h1[1][threadIdx.x] = 0.0f;
    if (threadIdx.x == 0) {
        g_ctrA.v = 0u;
        g_ctrB.v = 0u;
        g_ctrC.v = 0u;
        g_ctrD.v = 0u;
    }
}

// ---------------- launch -----------------------------------------------------
extern "C" void kernel_launch(void* const* d_in, const int* in_sizes, int n_in,
                              void* d_out, int out_size)
{
    const int*   idx  = (const int*)  d_in[0];
    const float* E    = (const float*)d_in[1];
    const float* Wih0 = (const float*)d_in[2];
    const float* Whh0 = (const float*)d_in[3];
    const float* bih0 = (const float*)d_in[4];
    const float* bhh0 = (const float*)d_in[5];
    const float* Wih1 = (const float*)d_in[6];
    const float* Whh1 = (const float*)d_in[7];
    const float* bih1 = (const float*)d_in[8];
    const float* bhh1 = (const float*)d_in[9];
    float* out = (float*)d_out;

    float *emb;
    cudaGetSymbolAddress((void**)&emb, g_emb);

    // 1) embedding + max-norm
    embed_kernel<<<L_SEQ, 128>>>(idx, E, emb);

    // 2) everything else in one fused wavefront kernel
    zero_state_kernel<<<1, 1024>>>();
    fused_kernel<<<NFUSED, 256>>>(Whh0, bhh0, Whh1, bhh1,
                                  Wih0, bih0, Wih1, bih1, out);
}

// round 15
// speedup vs baseline: 1.8043x; 1.0004x over previous
#include <cuda_runtime.h>
#include <math.h>

#define L_SEQ 4096
#define EDIM  512
#define HDIM  1024
#define G3    3072
#define CHUNK 128
#define NCHUNK (L_SEQ / CHUNK)      // 32
#define L0CTA 64
#define L1CTA 64
#define GEMCTA 20
#define NFUSED (L0CTA + L1CTA + GEMCTA)   // 148 = #SMs -> single wave guaranteed

// ---------------- scratch (static device globals; no allocation) -------------
__device__ float g_emb[(size_t)L_SEQ * EDIM];          // 8 MB
__device__ float g_gi0[(size_t)L_SEQ * G3];            // 50 MB
__device__ float g_gi1[(size_t)L_SEQ * G3];            // 50 MB
__device__ float g_ys [(size_t)L_SEQ * HDIM];          // 16 MB
__device__ float g_h0[2][HDIM];
__device__ float g_h1[2][HDIM];

struct __align__(128) CtrLine { unsigned v; unsigned pad[31]; };
__device__ CtrLine g_ctrA;   // layer-0 step counter  (+64 per tick)
__device__ CtrLine g_ctrB;   // gi1 chunk counter     (+20 per chunk)
__device__ CtrLine g_ctrC;   // layer-1 step counter  (+64 per tick)
__device__ CtrLine g_ctrD;   // gi0 chunk counter     (+20 per chunk)

// ---------------- memory-model helpers ---------------------------------------
__device__ __forceinline__ unsigned ldacq_u32(const unsigned* p)
{
    unsigned v;
    asm volatile("ld.acquire.gpu.global.b32 %0, [%1];" : "=r"(v) : "l"(p) : "memory");
    return v;
}
__device__ __forceinline__ void red_release_add(unsigned* p, unsigned v)
{
    asm volatile("red.release.gpu.global.add.u32 [%0], %1;" :: "l"(p), "r"(v) : "memory");
}
__device__ __forceinline__ float4 ldacq_v4(const float* p)
{
    float4 v;
    asm volatile("ld.acquire.gpu.global.v4.f32 {%0,%1,%2,%3}, [%4];"
                 : "=f"(v.x), "=f"(v.y), "=f"(v.z), "=f"(v.w) : "l"(p) : "memory");
    return v;
}

// ---------------- packed f32x2 helpers (sm_103a) ------------------------------
__device__ __forceinline__ unsigned long long pack2(float x, float y)
{
    unsigned long long r;
    asm("mov.b64 %0, {%1, %2};" : "=l"(r) : "f"(x), "f"(y));
    return r;
}
__device__ __forceinline__ unsigned long long fma2(unsigned long long a,
                                                   unsigned long long b,
                                                   unsigned long long c)
{
    unsigned long long d;
    asm("fma.rn.f32x2 %0, %1, %2, %3;" : "=l"(d) : "l"(a), "l"(b), "l"(c));
    return d;
}
__device__ __forceinline__ float2 unpack2(unsigned long long v)
{
    float2 f;
    asm("mov.b64 {%0, %1}, %2;" : "=f"(f.x), "=f"(f.y) : "l"(v));
    return f;
}

__device__ __forceinline__ float fsig(float x)
{
    return __fdividef(1.0f, 1.0f + __expf(-x));
}
__device__ __forceinline__ float ftanh(float x)
{
    return 1.0f - __fdividef(2.0f, 1.0f + __expf(2.0f * x));
}

// ---------------- embedding + max-norm --------------------------------------
__global__ void embed_kernel(const int* __restrict__ idx,
                             const float* __restrict__ E,
                             float* __restrict__ emb)
{
    int t = blockIdx.x;
    int id = idx[t];
    const float4* row = (const float4*)(E + (size_t)id * EDIM);
    float4 v = row[threadIdx.x];
    float ss = v.x*v.x + v.y*v.y + v.z*v.z + v.w*v.w;
    #pragma unroll
    for (int o = 16; o; o >>= 1) ss += __shfl_xor_sync(0xffffffffu, ss, o);
    __shared__ float red[4];
    int w = threadIdx.x >> 5;
    if ((threadIdx.x & 31) == 0) red[w] = ss;
    __syncthreads();
    float tot = red[0] + red[1] + red[2] + red[3];
    float scale = fminf(1.0f, 1.0f / fmaxf(sqrtf(tot), 1e-7f));
    v.x *= scale; v.y *= scale; v.z *= scale; v.w *= scale;
    ((float4*)(emb + (size_t)t * EDIM))[threadIdx.x] = v;
}

// ---------------- double-buffered f32x2 GEMM tile: 128x128, C = A@B^T + bias --
__device__ void gemm_tile_db(const float* __restrict__ Ab,
                             const float* __restrict__ Bb,
                             const float* __restrict__ bias,
                             float* __restrict__ Cb,
                             int ldc, int K)
{
    __shared__ float As[2][16][128];
    __shared__ float Bs[2][16][136];
    int tid = threadIdx.x;
    int tx = tid & 15, ty = tid >> 4;

    unsigned long long acc2[8][4];
    #pragma unroll
    for (int i = 0; i < 8; i++)
        #pragma unroll
        for (int j = 0; j < 4; j++) acc2[i][j] = 0ull;

    int q0 = tid,        r0 = q0 >> 2, c0 = q0 & 3;
    int q1 = tid + 256,  r1 = q1 >> 2, c1 = q1 & 3;

    float4 ra0, ra1, rb0, rb1;
    ra0 = *(const float4*)(Ab + (size_t)r0 * K + c0 * 4);
    rb0 = *(const float4*)(Bb + (size_t)r0 * K + c0 * 4);
    ra1 = *(const float4*)(Ab + (size_t)r1 * K + c1 * 4);
    rb1 = *(const float4*)(Bb + (size_t)r1 * K + c1 * 4);
    As[0][c0*4+0][r0] = ra0.x; As[0][c0*4+1][r0] = ra0.y; As[0][c0*4+2][r0] = ra0.z; As[0][c0*4+3][r0] = ra0.w;
    Bs[0][c0*4+0][r0] = rb0.x; Bs[0][c0*4+1][r0] = rb0.y; Bs[0][c0*4+2][r0] = rb0.z; Bs[0][c0*4+3][r0] = rb0.w;
    As[0][c1*4+0][r1] = ra1.x; As[0][c1*4+1][r1] = ra1.y; As[0][c1*4+2][r1] = ra1.z; As[0][c1*4+3][r1] = ra1.w;
    Bs[0][c1*4+0][r1] = rb1.x; Bs[0][c1*4+1][r1] = rb1.y; Bs[0][c1*4+2][r1] = rb1.z; Bs[0][c1*4+3][r1] = rb1.w;
    __syncthreads();

    int nb = K / 16;
    for (int kb = 0; kb < nb; kb++) {
        int buf = kb & 1;
        bool more = (kb + 1 < nb);
        if (more) {
            int k0 = (kb + 1) * 16;
            ra0 = *(const float4*)(Ab + (size_t)r0 * K + k0 + c0 * 4);
            rb0 = *(const float4*)(Bb + (size_t)r0 * K + k0 + c0 * 4);
            ra1 = *(const float4*)(Ab + (size_t)r1 * K + k0 + c1 * 4);
            rb1 = *(const float4*)(Bb + (size_t)r1 * K + k0 + c1 * 4);
        }
        #pragma unroll
        for (int k = 0; k < 16; k++) {
            float4 a0 = *(const float4*)&As[buf][k][ty*8];
            float4 a1 = *(const float4*)&As[buf][k][ty*8+4];
            float4 b0 = *(const float4*)&Bs[buf][k][tx*8];
            float4 b1 = *(const float4*)&Bs[buf][k][tx*8+4];
            float av[8] = {a0.x,a0.y,a0.z,a0.w,a1.x,a1.y,a1.z,a1.w};
            unsigned long long bp[4] = { pack2(b0.x,b0.y), pack2(b0.z,b0.w),
                                         pack2(b1.x,b1.y), pack2(b1.z,b1.w) };
            #pragma unroll
            for (int i = 0; i < 8; i++) {
                unsigned long long ad = pack2(av[i], av[i]);
                #pragma unroll
                for (int j = 0; j < 4; j++)
                    acc2[i][j] = fma2(ad, bp[j], acc2[i][j]);
            }
        }
        if (more) {
            int nbuf = (kb + 1) & 1;
            As[nbuf][c0*4+0][r0] = ra0.x; As[nbuf][c0*4+1][r0] = ra0.y; As[nbuf][c0*4+2][r0] = ra0.z; As[nbuf][c0*4+3][r0] = ra0.w;
            Bs[nbuf][c0*4+0][r0] = rb0.x; Bs[nbuf][c0*4+1][r0] = rb0.y; Bs[nbuf][c0*4+2][r0] = rb0.z; Bs[nbuf][c0*4+3][r0] = rb0.w;
            As[nbuf][c1*4+0][r1] = ra1.x; As[nbuf][c1*4+1][r1] = ra1.y; As[nbuf][c1*4+2][r1] = ra1.z; As[nbuf][c1*4+3][r1] = ra1.w;
            Bs[nbuf][c1*4+0][r1] = rb1.x; Bs[nbuf][c1*4+1][r1] = rb1.y; Bs[nbuf][c1*4+2][r1] = rb1.z; Bs[nbuf][c1*4+3][r1] = rb1.w;
            __syncthreads();
        }
    }

    float bb[8];
    #pragma unroll
    for (int j = 0; j < 8; j++) bb[j] = bias[tx*8 + j];
    #pragma unroll
    for (int i = 0; i < 8; i++) {
        size_t row = (size_t)(ty*8 + i);
        float2 e0 = unpack2(acc2[i][0]);
        float2 e1 = unpack2(acc2[i][1]);
        float2 e2 = unpack2(acc2[i][2]);
        float2 e3 = unpack2(acc2[i][3]);
        float4 o0 = make_float4(e0.x+bb[0], e0.y+bb[1], e1.x+bb[2], e1.y+bb[3]);
        float4 o1 = make_float4(e2.x+bb[4], e2.y+bb[5], e3.x+bb[6], e3.y+bb[7]);
        *(float4*)(Cb + row * ldc + tx*8    ) = o0;
        *(float4*)(Cb + row * ldc + tx*8 + 4) = o1;
    }
    __syncthreads();   // smem safe for next tile; orders C stores before release
}

// produce one 128-token chunk of an input projection
__device__ void produce_chunk(int g, const float* A, int K,
                              const float* W, const float* bias,
                              float* C, int ch)
{
    for (int tn = g; tn < G3 / 128; tn += GEMCTA) {
        gemm_tile_db(A + (size_t)(ch * CHUNK) * K,
                     W + (size_t)(tn * 128) * K,
                     bias + tn * 128,
                     C + (size_t)(ch * CHUNK) * G3 + tn * 128,
                     G3, K);
    }
}

// ---------------- fused wavefront kernel --------------------------------------
// CTAs [0,64)    : layer-0 scan (ctrA), gated by ctrD at chunk boundaries
// CTAs [64,128)  : layer-1 scan (ctrC), gated by ctrB at chunk boundaries
// CTAs [128,148) : GEMM group: pre gi0[0..1]; per ch: gi1[ch], gi0[ch+2]
// Scan: R11 FMA layout (h read once per lane) + split-tree reduction
// (6 shfl + 3 sel + 12 shfl = 18 shfl) + half-warp gates/publish.
__global__ void __launch_bounds__(256, 1) fused_kernel(
    const float* __restrict__ Whh0, const float* __restrict__ bhh0,
    const float* __restrict__ Whh1, const float* __restrict__ bhh1,
    const float* __restrict__ Wih0, const float* __restrict__ bih0,
    const float* __restrict__ Wih1, const float* __restrict__ bih1,
    float* __restrict__ out)
{
    int blk = blockIdx.x;
    int tid = threadIdx.x;

    if (blk >= L0CTA + L1CTA) {
        // ---------------- GEMM group ----------------
        int g = blk - (L0CTA + L1CTA);
        for (int ch = 0; ch < 2; ch++) {
            produce_chunk(g, g_emb, EDIM, Wih0, bih0, g_gi0, ch);
            if (tid == 0) red_release_add(&g_ctrD.v, 1u);
        }
        for (int ch = 0; ch < NCHUNK; ch++) {
            if (tid == 0) {
                unsigned tgt = 64u * (unsigned)(CHUNK * (ch + 1));
                while ((int)(ldacq_u32(&g_ctrA.v) - tgt) < 0) { }
            }
            __syncthreads();
            produce_chunk(g, g_ys, HDIM, Wih1, bih1, g_gi1, ch);
            if (tid == 0) red_release_add(&g_ctrB.v, 1u);
            if (ch + 2 < NCHUNK) {
                produce_chunk(g, g_emb, EDIM, Wih0, bih0, g_gi0, ch + 2);
                if (tid == 0) red_release_add(&g_ctrD.v, 1u);
            }
        }
        return;
    }

    // ---------------- scan roles ----------------
    int layer = (blk >= L0CTA) ? 1 : 0;
    int cb    = layer ? blk - L0CTA : blk;
    int w     = tid >> 5;
    int lane  = tid & 31;
    int hl    = lane & 15;                    // lane within half-warp
    int jj    = lane >> 4;                    // which unit of the pair (for gates)
    int u0    = cb * 16 + 2 * w;              // warp owns units u0, u0+1
    int unit  = u0 + jj;                      // this half-warp's unit (gate phase)

    const float* Whh = layer ? Whh1 : Whh0;
    const float* bhh = layer ? bhh1 : bhh0;
    const float* gi  = layer ? g_gi1 : g_gi0;
    unsigned* stepctr  = layer ? &g_ctrC.v : &g_ctrA.v;
    unsigned* chunkctr = layer ? &g_ctrB.v : &g_ctrD.v;

    // R11 weight layout: both units' rows in-lane; lane covers h[c*128+lane*4)
    ulonglong2 wr2[2][8], wz2[2][8], wn2[2][8];
    #pragma unroll
    for (int j = 0; j < 2; j++) {
        const ulonglong2* Wr = (const ulonglong2*)(Whh + (size_t)(u0+j)          * HDIM);
        const ulonglong2* Wz = (const ulonglong2*)(Whh + (size_t)(HDIM   + u0+j) * HDIM);
        const ulonglong2* Wn = (const ulonglong2*)(Whh + (size_t)(2*HDIM + u0+j) * HDIM);
        #pragma unroll
        for (int c = 0; c < 8; c++) {
            wr2[j][c] = Wr[c*32 + lane];
            wz2[j][c] = Wz[c*32 + lane];
            wn2[j][c] = Wn[c*32 + lane];
        }
    }
    // per-lane biases for THIS half-warp's unit (direct load, no runtime index)
    float brj = bhh[unit];
    float bzj = bhh[HDIM   + unit];
    float bnj = bhh[2*HDIM + unit];

    __shared__ __align__(16) float h_s[HDIM];
    __shared__ float gi_s[2][48];              // double-buffered (pipelined)
    float h_last = 0.0f;

    size_t gi_off = (size_t)(tid >> 4) * HDIM + cb * 16 + (tid & 15);

    for (int t = 0; t < L_SEQ; t++) {
        bool boundary = (t & (CHUNK - 1)) == 0;
        bool pre_next = ((t + 1) & (CHUNK - 1)) != 0 && (t + 1) < L_SEQ;

        // warp 0: chunk gate (rare) + 4-lane cooperative step poll
        if (w == 0) {
            if (boundary && lane == 0) {
                unsigned tb = (unsigned)GEMCTA * ((unsigned)(t >> 7) + 1u);
                while ((int)(ldacq_u32(chunkctr) - tb) < 0) { }
            }
            __syncwarp();
            unsigned tgt = 64u * (unsigned)t;
            for (;;) {
                unsigned v = (lane < 4) ? ldacq_u32(stepctr) : 0u;
                bool sat = (lane < 4) && ((int)(v - tgt) >= 0);
                if (__any_sync(0xffffffffu, sat)) break;
            }
        }
        __syncthreads();                       // bar#1

        if (boundary && tid < 48)
            gi_s[t & 1][tid] = gi[(size_t)t * G3 + gi_off];

        const float* hb = layer ? g_h1[t & 1] : g_h0[t & 1];
        float4 hv = ldacq_v4(hb + tid * 4);
        *(float4*)&h_s[tid * 4] = hv;
        __syncthreads();                       // bar#2

        float gnext = 0.0f;
        if (pre_next && tid < 48)
            gnext = gi[(size_t)(t + 1) * G3 + gi_off];

        // FMA phase: h read ONCE per lane, serves both units (32KB LDS/CTA)
        unsigned long long ar2[2] = {0ull, 0ull}, az2[2] = {0ull, 0ull}, an2[2] = {0ull, 0ull};
        #pragma unroll
        for (int c = 0; c < 8; c++) {
            ulonglong2 h2 = *(const ulonglong2*)&h_s[c*128 + lane*4];
            #pragma unroll
            for (int j = 0; j < 2; j++) {
                ar2[j] = fma2(wr2[j][c].x, h2.x, ar2[j]);
                az2[j] = fma2(wz2[j][c].x, h2.x, az2[j]);
                an2[j] = fma2(wn2[j][c].x, h2.x, an2[j]);
                ar2[j] = fma2(wr2[j][c].y, h2.y, ar2[j]);
                az2[j] = fma2(wz2[j][c].y, h2.y, az2[j]);
                an2[j] = fma2(wn2[j][c].y, h2.y, an2[j]);
            }
        }
        float2 f;
        f = unpack2(ar2[0]); float s0r = f.x + f.y;
        f = unpack2(az2[0]); float s0z = f.x + f.y;
        f = unpack2(an2[0]); float s0n = f.x + f.y;
        f = unpack2(ar2[1]); float s1r = f.x + f.y;
        f = unpack2(az2[1]); float s1z = f.x + f.y;
        f = unpack2(an2[1]); float s1n = f.x + f.y;

        // split-tree reduction: level 16 on all 6, then half-warps specialize
        s0r += __shfl_xor_sync(0xffffffffu, s0r, 16);
        s0z += __shfl_xor_sync(0xffffffffu, s0z, 16);
        s0n += __shfl_xor_sync(0xffffffffu, s0n, 16);
        s1r += __shfl_xor_sync(0xffffffffu, s1r, 16);
        s1z += __shfl_xor_sync(0xffffffffu, s1z, 16);
        s1n += __shfl_xor_sync(0xffffffffu, s1n, 16);
        float sr = jj ? s1r : s0r;
        float sz = jj ? s1z : s0z;
        float sn = jj ? s1n : s0n;
        #pragma unroll
        for (int o = 8; o; o >>= 1) {          // stays within each half-warp
            sr += __shfl_xor_sync(0xffffffffu, sr, o);
            sz += __shfl_xor_sync(0xffffffffu, sz, o);
            sn += __shfl_xor_sync(0xffffffffu, sn, o);
        }

        if (pre_next && tid < 48)
            gi_s[(t + 1) & 1][tid] = gnext;

        // gates: half-warp handles its unit
        float xr = gi_s[t & 1][      2*w + jj];
        float xz = gi_s[t & 1][16 +  2*w + jj];
        float xn = gi_s[t & 1][32 +  2*w + jj];
        float r = fsig(xr + sr + brj);
        float z = fsig(xz + sz + bzj);
        float n = ftanh(xn + r * (sn + bnj));
        float hp = h_s[unit];
        float hnw = (1.0f - z) * n + z * hp;
        if (hl == 0) {                         // lanes 0 and 16 publish
            float* hout = layer ? g_h1[(t + 1) & 1] : g_h0[(t + 1) & 1];
            hout[unit] = hnw;
            if (!layer) g_ys[(size_t)t * HDIM + unit] = hnw;
            h_last = hnw;
        }
        __syncthreads();                       // bar#3: stores + gi stage visible
        if (tid == 0)
            red_release_add(stepctr, 1u);
    }

    if (hl == 0) {
        if (!layer) {                          // h1 -> out[1024:2048]
            out[HDIM + unit] = h_last;
        } else {                               // ys2[-1]=h2 -> out[0:1024]; h2 -> out[2048:3072]
            out[unit]          = h_last;
            out[2*HDIM + unit] = h_last;
        }
    }
}

// reset: h buffers = 0, counters = 0
__global__ void zero_state_kernel()
{
    g_h0[0][threadIdx.x] = 0.0f;
    g_h0[1][threadIdx.x] = 0.0f;
    g_h1[0][threadIdx.x] = 0.0f;
    g_h1[1][threadIdx.x] = 0.0f;
    if (threadIdx.x == 0) {
        g_ctrA.v = 0u;
        g_ctrB.v = 0u;
        g_ctrC.v = 0u;
        g_ctrD.v = 0u;
    }
}

// ---------------- launch -----------------------------------------------------
extern "C" void kernel_launch(void* const* d_in, const int* in_sizes, int n_in,
                              void* d_out, int out_size)
{
    const int*   idx  = (const int*)  d_in[0];
    const float* E    = (const float*)d_in[1];
    const float* Wih0 = (const float*)d_in[2];
    const float* Whh0 = (const float*)d_in[3];
    const float* bih0 = (const float*)d_in[4];
    const float* bhh0 = (const float*)d_in[5];
    const float* Wih1 = (const float*)d_in[6];
    const float* Whh1 = (const float*)d_in[7];
    const float* bih1 = (const float*)d_in[8];
    const float* bhh1 = (const float*)d_in[9];
    float* out = (float*)d_out;

    float *emb;
    cudaGetSymbolAddress((void**)&emb, g_emb);

    // 1) embedding + max-norm
    embed_kernel<<<L_SEQ, 128>>>(idx, E, emb);

    // 2) everything else in one fused wavefront kernel
    zero_state_kernel<<<1, 1024>>>();
    fused_kernel<<<NFUSED, 256>>>(Whh0, bhh0, Whh1, bhh1,
                                  Wih0, bih0, Wih1, bih1, out);
}